// round 1
// baseline (speedup 1.0000x reference)
#include <cuda_runtime.h>
#include <cstdint>
#include <cstddef>

#define BB 16
#define LL 32768
#define HH 64
#define NN 16
#define DMM 32

typedef unsigned long long u64;

// ---------------- scratch (device globals; no allocation allowed) ----------------
__device__ float g_u[(size_t)BB * HH * LL];   // gelu(x@W_lin) transposed to [B,H,L]
__device__ float g_z[(size_t)BB * HH * LL];   // FiLM-affine SSM output [B,H,L]
__device__ __align__(16) float g_wre[HH * NN];
__device__ __align__(16) float g_wim[HH * NN];
__device__ __align__(16) float g_cre[HH * NN];   // 2*Re(C')
__device__ __align__(16) float g_cim[HH * NN];   // 2*Im(C')
__device__ float g_wTre[HH * NN], g_wTim[HH * NN];     // w^128
__device__ float g_wT16re[HH * NN], g_wT16im[HH * NN]; // w^2048
__device__ float g_gamma[BB * HH], g_beta[BB * HH];

// ---------------- f32x2 helpers (FFMA2: full-rate fp32 on sm_103a) ----------------
__device__ __forceinline__ u64 pk(float lo, float hi) {
    u64 r; asm("mov.b64 %0, {%1,%2};" : "=l"(r) : "f"(lo), "f"(hi)); return r;
}
__device__ __forceinline__ void upk(u64 a, float& lo, float& hi) {
    asm("mov.b64 {%0,%1}, %2;" : "=f"(lo), "=f"(hi) : "l"(a));
}
__device__ __forceinline__ u64 fma2(u64 a, u64 b, u64 c) {
    u64 d; asm("fma.rn.f32x2 %0, %1, %2, %3;" : "=l"(d) : "l"(a), "l"(b), "l"(c)); return d;
}
__device__ __forceinline__ u64 mul2(u64 a, u64 b) {
    u64 d; asm("mul.rn.f32x2 %0, %1, %2;" : "=l"(d) : "l"(a), "l"(b)); return d;
}
__device__ __forceinline__ u64 add2(u64 a, u64 b) {
    u64 d; asm("add.rn.f32x2 %0, %1, %2;" : "=l"(d) : "l"(a), "l"(b)); return d;
}
#define NEGMASK 0x8000000080000000ULL

// jax.nn.gelu (approximate=True): 0.5*x*(1+tanh(sqrt(2/pi)*(x+0.044715*x^3)))
__device__ __forceinline__ float gelu_f(float x) {
    float x3 = x * x * x;
    float z = 0.7978845608028654f * fmaf(0.044715f, x3, x);
    float az = fabsf(z);
    float e = __expf(2.0f * az);                 // inf for large az -> t = 1
    float t = 1.0f - __fdividef(2.0f, e + 1.0f);
    t = copysignf(t, z);
    return 0.5f * x * (1.0f + t);
}

// ---------------- K1: conditioning MLP + FiLM + SSM constants ----------------
__global__ void k_setup(const float* __restrict__ cp,
                        const float* __restrict__ W0, const float* __restrict__ b0,
                        const float* __restrict__ W1, const float* __restrict__ b1,
                        const float* __restrict__ W2, const float* __restrict__ b2,
                        const float* __restrict__ log_dt,
                        const float* __restrict__ A_re, const float* __restrict__ A_im,
                        const float* __restrict__ C_re, const float* __restrict__ C_im,
                        const float* __restrict__ W_film, const float* __restrict__ b_film)
{
    __shared__ float c0[BB * DMM];
    __shared__ float c1[BB * DMM];
    int t = threadIdx.x;

    // layer 0: [B,2] @ [2,DM]
    for (int i = t; i < BB * DMM; i += blockDim.x) {
        int b = i / DMM, d = i % DMM;
        float v = fmaf(cp[b * 2 + 0], W0[d], fmaf(cp[b * 2 + 1], W0[DMM + d], b0[d]));
        c0[i] = gelu_f(v);
    }
    __syncthreads();
    // layer 1
    for (int i = t; i < BB * DMM; i += blockDim.x) {
        int b = i / DMM, d = i % DMM;
        float v = b1[d];
        for (int k = 0; k < DMM; k++) v = fmaf(c0[b * DMM + k], W1[k * DMM + d], v);
        c1[i] = gelu_f(v);
    }
    __syncthreads();
    // layer 2
    for (int i = t; i < BB * DMM; i += blockDim.x) {
        int b = i / DMM, d = i % DMM;
        float v = b2[d];
        for (int k = 0; k < DMM; k++) v = fmaf(c1[b * DMM + k], W2[k * DMM + d], v);
        c0[i] = gelu_f(v);
    }
    __syncthreads();
    // FiLM: [B,DM] @ [DM,2H]
    for (int i = t; i < BB * 2 * HH; i += blockDim.x) {
        int b = i / (2 * HH), j = i % (2 * HH);
        float v = b_film[j];
        for (int k = 0; k < DMM; k++) v = fmaf(c0[b * DMM + k], W_film[k * 2 * HH + j], v);
        if (j < HH) g_gamma[b * HH + j] = v;
        else        g_beta[b * HH + j - HH] = v;
    }
    // SSM constants
    for (int i = t; i < HH * NN; i += blockDim.x) {
        int h = i / NN;
        float dt = expf(log_dt[h]);
        float ar = A_re[i], ai = A_im[i];
        float dre = dt * ar, dim = dt * ai;
        float e = expf(dre);
        float wre = e * cosf(dim), wim = e * sinf(dim);
        g_wre[i] = wre; g_wim[i] = wim;
        float inv = 1.0f / (ar * ar + ai * ai);
        float nre = wre - 1.0f, nim = wim;                 // exp(dtA)-1
        float qre = (nre * ar + nim * ai) * inv;           // (w-1)/A
        float qim = (nim * ar - nre * ai) * inv;
        float cr = C_re[i], ci = C_im[i];
        g_cre[i] = 2.0f * (cr * qre - ci * qim);
        g_cim[i] = 2.0f * (cr * qim + ci * qre);
        // chunk-jump powers in double (phase can be hundreds of radians)
        double mre = (double)dre, mim = (double)dim;
        double eg = exp(128.0 * mre);
        g_wTre[i] = (float)(eg * cos(128.0 * mim));
        g_wTim[i] = (float)(eg * sin(128.0 * mim));
        double eg2 = exp(2048.0 * mre);
        g_wT16re[i] = (float)(eg2 * cos(2048.0 * mim));
        g_wT16im[i] = (float)(eg2 * sin(2048.0 * mim));
    }
}

// ---------------- K2: u = gelu(x @ W_lin + b_lin), write transposed [B,H,L] ----------------
// grid: BB * (LL/256) blocks, 256 threads. l-tile = 256. Thread: (li = t&63) owns
// 4 l's {li, li+64, li+128, li+192} and 16 h's [hb, hb+16).
__global__ __launch_bounds__(256) void k_linear(const float* __restrict__ x,
                                                const float* __restrict__ W,
                                                const float* __restrict__ bias)
{
    extern __shared__ float sm2[];
    float* xs = sm2;                 // [256][65]
    float* Ws = sm2 + 256 * 65;      // [64][64], 16B-aligned offset (66560 B)
    int t = threadIdx.x;
    int b = blockIdx.x >> 7;         // 128 tiles per batch
    int tile = blockIdx.x & 127;
    int l0 = tile * 256;
    const float* xg = x + ((size_t)b * LL + l0) * HH;

    for (int i = t; i < 64 * 64; i += 256) Ws[i] = W[i];
    for (int i = t; i < 256 * 64; i += 256) {
        int l = i >> 6, k = i & 63;
        xs[l * 65 + k] = xg[i];
    }
    __syncthreads();

    int li = t & 63;
    int hb = (t >> 6) * 16;
    u64 acc[4][8];
    #pragma unroll
    for (int p = 0; p < 8; p++) {
        u64 bp = *reinterpret_cast<const u64*>(bias + hb + 2 * p);
        acc[0][p] = bp; acc[1][p] = bp; acc[2][p] = bp; acc[3][p] = bp;
    }
    for (int k = 0; k < 64; k++) {
        float x0 = xs[li * 65 + k];
        float x1 = xs[(li + 64) * 65 + k];
        float x2v = xs[(li + 128) * 65 + k];
        float x3 = xs[(li + 192) * 65 + k];
        u64 xa = pk(x0, x0), xb = pk(x1, x1), xc = pk(x2v, x2v), xd = pk(x3, x3);
        const u64* wrow = reinterpret_cast<const u64*>(Ws + k * 64 + hb);
        #pragma unroll
        for (int p = 0; p < 8; p++) {
            u64 w2 = wrow[p];
            acc[0][p] = fma2(xa, w2, acc[0][p]);
            acc[1][p] = fma2(xb, w2, acc[1][p]);
            acc[2][p] = fma2(xc, w2, acc[2][p]);
            acc[3][p] = fma2(xd, w2, acc[3][p]);
        }
    }
    #pragma unroll
    for (int lg = 0; lg < 4; lg++) {
        int l = l0 + li + lg * 64;
        #pragma unroll
        for (int p = 0; p < 8; p++) {
            float v0, v1; upk(acc[lg][p], v0, v1);
            int h0 = hb + 2 * p;
            g_u[((size_t)b * HH + h0) * LL + l] = gelu_f(v0);
            g_u[((size_t)b * HH + h0 + 1) * LL + l] = gelu_f(v1);
        }
    }
}

// ---------------- K3: chunked parallel scan per (b,h); writes z = y*gamma+beta ----------------
// 1024 blocks (one per (b,h)), 256 threads, chunk T=128. Whole sequence in SMEM.
__global__ __launch_bounds__(256) void k_scan(const float* __restrict__ Dp)
{
    extern __shared__ float sm[];
    float* su = sm;                                          // 32768 floats
    float2* sst = reinterpret_cast<float2*>(sm + LL);        // [256][16]
    float2* gs = reinterpret_cast<float2*>(sm + LL + 256 * 16 * 2); // [16][16]
    int t = threadIdx.x;
    int bh = blockIdx.x;
    int h = bh & 63;

    const float4* gu4 = reinterpret_cast<const float4*>(g_u + (size_t)bh * LL);
    float4* sv4 = reinterpret_cast<float4*>(su);
    for (int i = t; i < LL / 4; i += 256) sv4[i] = gu4[i];

    // per-h constants as n-pair f32x2
    u64 wre2[8], wim2[8], nwim2[8], cre2[8], ncim2[8];
    {
        const u64* pwre = reinterpret_cast<const u64*>(g_wre + h * NN);
        const u64* pwim = reinterpret_cast<const u64*>(g_wim + h * NN);
        const u64* pcre = reinterpret_cast<const u64*>(g_cre + h * NN);
        const u64* pcim = reinterpret_cast<const u64*>(g_cim + h * NN);
        #pragma unroll
        for (int p = 0; p < 8; p++) {
            wre2[p] = pwre[p];
            wim2[p] = pwim[p];
            nwim2[p] = pwim[p] ^ NEGMASK;
            cre2[p] = pcre[p];
            ncim2[p] = pcim[p] ^ NEGMASK;
        }
    }
    __syncthreads();

    int off = t * 128;
    u64 sre[8], sim[8];
    #pragma unroll
    for (int p = 0; p < 8; p++) { sre[p] = 0ULL; sim[p] = 0ULL; }

    // ---- pass 1: local chunk scan (zero init) ----
    #pragma unroll 1
    for (int j4 = 0; j4 < 32; j4++) {
        float4 uv = *reinterpret_cast<float4*>(su + off + j4 * 4);
        float us[4] = {uv.x, uv.y, uv.z, uv.w};
        #pragma unroll
        for (int s = 0; s < 4; s++) {
            u64 u2 = pk(us[s], us[s]);
            #pragma unroll
            for (int p = 0; p < 8; p++) {
                u64 t0 = fma2(nwim2[p], sim[p], u2);
                u64 nre = fma2(wre2[p], sre[p], t0);
                sim[p] = fma2(wre2[p], sim[p], mul2(wim2[p], sre[p]));
                sre[p] = nre;
            }
        }
    }
    #pragma unroll
    for (int p = 0; p < 8; p++) {
        float r0, r1, i0, i1; upk(sre[p], r0, r1); upk(sim[p], i0, i1);
        sst[t * 16 + 2 * p] = make_float2(r0, i0);
        sst[t * 16 + 2 * p + 1] = make_float2(r1, i1);
    }
    __syncthreads();

    // ---- combine: 2-level scan over 256 chunk states (16 n x 16 groups) ----
    int n = t & 15, g = t >> 4;
    float wtr = g_wTre[h * NN + n], wti = g_wTim[h * NN + n];
    {   // level 1: group totals (zero-init)
        float Ir = 0.f, Ii = 0.f;
        for (int j = 0; j < 16; j++) {
            float2 loc = sst[(g * 16 + j) * 16 + n];
            float nr = fmaf(wtr, Ir, fmaf(-wti, Ii, loc.x));
            Ii = fmaf(wtr, Ii, fmaf(wti, Ir, loc.y));
            Ir = nr;
        }
        gs[g * 16 + n] = make_float2(Ir, Ii);
    }
    __syncthreads();
    if (t < 16) {   // level 2: sequential over 16 groups with w^2048
        float wr = g_wT16re[h * NN + t], wi = g_wT16im[h * NN + t];
        float Pr = 0.f, Pi = 0.f;
        for (int gg = 0; gg < 16; gg++) {
            float2 tmp = gs[gg * 16 + t];
            gs[gg * 16 + t] = make_float2(Pr, Pi);
            float nr = fmaf(wr, Pr, fmaf(-wi, Pi, tmp.x));
            Pi = fmaf(wr, Pi, fmaf(wi, Pr, tmp.y));
            Pr = nr;
        }
    }
    __syncthreads();
    {   // level 3: per-chunk incoming states (overwrite sst in place)
        float2 I0 = gs[g * 16 + n];
        float Ir = I0.x, Ii = I0.y;
        for (int j = 0; j < 16; j++) {
            int c = g * 16 + j;
            float2 loc = sst[c * 16 + n];
            sst[c * 16 + n] = make_float2(Ir, Ii);
            float nr = fmaf(wtr, Ir, fmaf(-wti, Ii, loc.x));
            Ii = fmaf(wtr, Ii, fmaf(wti, Ir, loc.y));
            Ir = nr;
        }
    }
    __syncthreads();

    // ---- pass 2: rescan with incoming state, emit z = (y)*gamma + beta ----
    #pragma unroll
    for (int p = 0; p < 8; p++) {
        float2 a = sst[t * 16 + 2 * p];
        float2 bq = sst[t * 16 + 2 * p + 1];
        sre[p] = pk(a.x, bq.x);
        sim[p] = pk(a.y, bq.y);
    }
    float dcoef = Dp[h];
    float gam = g_gamma[bh];
    float bet = g_beta[bh];

    #pragma unroll 1
    for (int j4 = 0; j4 < 32; j4++) {
        float4 uv = *reinterpret_cast<float4*>(su + off + j4 * 4);
        float us[4] = {uv.x, uv.y, uv.z, uv.w};
        float zs[4];
        #pragma unroll
        for (int s = 0; s < 4; s++) {
            u64 u2 = pk(us[s], us[s]);
            u64 accA = 0ULL, accB = 0ULL;
            #pragma unroll
            for (int p = 0; p < 8; p++) {
                u64 t0 = fma2(nwim2[p], sim[p], u2);
                u64 nre = fma2(wre2[p], sre[p], t0);
                sim[p] = fma2(wre2[p], sim[p], mul2(wim2[p], sre[p]));
                sre[p] = nre;
                accA = fma2(cre2[p], nre, accA);
                accB = fma2(ncim2[p], sim[p], accB);
            }
            u64 acc = add2(accA, accB);
            float alo, ahi; upk(acc, alo, ahi);
            float y = alo + ahi;
            y = fmaf(dcoef, us[s], y);
            zs[s] = fmaf(y, gam, bet);
        }
        *reinterpret_cast<float4*>(su + off + j4 * 4) = make_float4(zs[0], zs[1], zs[2], zs[3]);
    }
    __syncthreads();

    float4* gz4 = reinterpret_cast<float4*>(g_z + (size_t)bh * LL);
    for (int i = t; i < LL / 4; i += 256) gz4[i] = sv4[i];
}

// ---------------- K4: out[b,l,h] = x[b,l,h] * gelu(z[b,h,l]) (SMEM transpose) ----------------
__global__ __launch_bounds__(256) void k_epilogue(const float* __restrict__ x,
                                                  float* __restrict__ out)
{
    __shared__ float zt[64 * 65];
    int t = threadIdx.x;
    int b = blockIdx.x >> 9;      // 512 tiles per batch
    int tile = blockIdx.x & 511;
    int l0 = tile * 64;
    for (int i = t; i < 64 * 64; i += 256) {
        int h = i >> 6, l = i & 63;
        zt[h * 65 + l] = g_z[((size_t)b * HH + h) * LL + l0 + l];
    }
    __syncthreads();
    const float* xg = x + ((size_t)b * LL + l0) * HH;
    float* og = out + ((size_t)b * LL + l0) * HH;
    for (int i = t; i < 64 * 64; i += 256) {
        int l = i >> 6, hh = i & 63;
        float z = zt[hh * 65 + l];
        og[i] = xg[i] * gelu_f(z);
    }
}

// ---------------- launch ----------------
extern "C" void kernel_launch(void* const* d_in, const int* in_sizes, int n_in,
                              void* d_out, int out_size)
{
    const float* x      = (const float*)d_in[0];
    const float* cp     = (const float*)d_in[1];
    const float* W0     = (const float*)d_in[2];
    const float* b0     = (const float*)d_in[3];
    const float* W1     = (const float*)d_in[4];
    const float* b1     = (const float*)d_in[5];
    const float* W2     = (const float*)d_in[6];
    const float* b2     = (const float*)d_in[7];
    const float* W_lin  = (const float*)d_in[8];
    const float* b_lin  = (const float*)d_in[9];
    const float* log_dt = (const float*)d_in[10];
    const float* A_re   = (const float*)d_in[11];
    const float* A_im   = (const float*)d_in[12];
    const float* C_re   = (const float*)d_in[13];
    const float* C_im   = (const float*)d_in[14];
    const float* Dv     = (const float*)d_in[15];
    const float* W_film = (const float*)d_in[16];
    const float* b_film = (const float*)d_in[17];
    float* out = (float*)d_out;

    const int smem_lin  = (256 * 65 + 64 * 64) * 4;               // 82944 B
    const int smem_scan = (LL + 256 * 16 * 2 + 16 * 16 * 2) * 4;  // 165888 B
    cudaFuncSetAttribute(k_linear, cudaFuncAttributeMaxDynamicSharedMemorySize, smem_lin);
    cudaFuncSetAttribute(k_scan, cudaFuncAttributeMaxDynamicSharedMemorySize, smem_scan);

    k_setup<<<1, 256>>>(cp, W0, b0, W1, b1, W2, b2,
                        log_dt, A_re, A_im, C_re, C_im, W_film, b_film);
    k_linear<<<BB * (LL / 256), 256, smem_lin>>>(x, W_lin, b_lin);
    k_scan<<<BB * HH, 256, smem_scan>>>(Dv);
    k_epilogue<<<BB * (LL / 64), 256>>>(x, out);
}

// round 2
// speedup vs baseline: 1.4105x; 1.4105x over previous
#include <cuda_runtime.h>
#include <cstdint>
#include <cstddef>

#define BB 16
#define LL 32768
#define HH 64
#define NN 16
#define DMM 32

typedef unsigned long long u64;

// ---------------- scratch (device globals; no allocation allowed) ----------------
__device__ float g_u[(size_t)BB * HH * LL];   // gelu(x@W_lin) transposed to [B,H,L]
__device__ float g_z[(size_t)BB * HH * LL];   // FiLM-affine SSM output [B,H,L]
__device__ __align__(16) float g_wre[HH * NN];
__device__ __align__(16) float g_wim[HH * NN];
__device__ __align__(16) float g_cre[HH * NN];   // 2*Re(C')
__device__ __align__(16) float g_cim[HH * NN];   // 2*Im(C')
__device__ float g_wTre[HH * NN], g_wTim[HH * NN];     // w^128
__device__ float g_wT16re[HH * NN], g_wT16im[HH * NN]; // w^2048
__device__ float g_gamma[BB * HH], g_beta[BB * HH];

// ---------------- f32x2 helpers (FFMA2: full-rate fp32 on sm_103a) ----------------
__device__ __forceinline__ u64 pk(float lo, float hi) {
    u64 r; asm("mov.b64 %0, {%1,%2};" : "=l"(r) : "f"(lo), "f"(hi)); return r;
}
__device__ __forceinline__ void upk(u64 a, float& lo, float& hi) {
    asm("mov.b64 {%0,%1}, %2;" : "=f"(lo), "=f"(hi) : "l"(a));
}
__device__ __forceinline__ u64 fma2(u64 a, u64 b, u64 c) {
    u64 d; asm("fma.rn.f32x2 %0, %1, %2, %3;" : "=l"(d) : "l"(a), "l"(b), "l"(c)); return d;
}
__device__ __forceinline__ u64 mul2(u64 a, u64 b) {
    u64 d; asm("mul.rn.f32x2 %0, %1, %2;" : "=l"(d) : "l"(a), "l"(b)); return d;
}
__device__ __forceinline__ u64 add2(u64 a, u64 b) {
    u64 d; asm("add.rn.f32x2 %0, %1, %2;" : "=l"(d) : "l"(a), "l"(b)); return d;
}
#define NEGMASK 0x8000000080000000ULL

// jax.nn.gelu (approximate=True): 0.5*x*(1+tanh(sqrt(2/pi)*(x+0.044715*x^3)))
__device__ __forceinline__ float gelu_f(float x) {
    float x3 = x * x * x;
    float z = 0.7978845608028654f * fmaf(0.044715f, x3, x);
    float az = fabsf(z);
    float e = __expf(2.0f * az);                 // inf for large az -> t = 1
    float t = 1.0f - __fdividef(2.0f, e + 1.0f);
    t = copysignf(t, z);
    return 0.5f * x * (1.0f + t);
}

// ---------------- K1: conditioning MLP + FiLM + SSM constants ----------------
__global__ void k_setup(const float* __restrict__ cp,
                        const float* __restrict__ W0, const float* __restrict__ b0,
                        const float* __restrict__ W1, const float* __restrict__ b1,
                        const float* __restrict__ W2, const float* __restrict__ b2,
                        const float* __restrict__ log_dt,
                        const float* __restrict__ A_re, const float* __restrict__ A_im,
                        const float* __restrict__ C_re, const float* __restrict__ C_im,
                        const float* __restrict__ W_film, const float* __restrict__ b_film)
{
    __shared__ float c0[BB * DMM];
    __shared__ float c1[BB * DMM];
    int t = threadIdx.x;

    // layer 0: [B,2] @ [2,DM]
    for (int i = t; i < BB * DMM; i += blockDim.x) {
        int b = i / DMM, d = i % DMM;
        float v = fmaf(cp[b * 2 + 0], W0[d], fmaf(cp[b * 2 + 1], W0[DMM + d], b0[d]));
        c0[i] = gelu_f(v);
    }
    __syncthreads();
    // layer 1
    for (int i = t; i < BB * DMM; i += blockDim.x) {
        int b = i / DMM, d = i % DMM;
        float v = b1[d];
        for (int k = 0; k < DMM; k++) v = fmaf(c0[b * DMM + k], W1[k * DMM + d], v);
        c1[i] = gelu_f(v);
    }
    __syncthreads();
    // layer 2
    for (int i = t; i < BB * DMM; i += blockDim.x) {
        int b = i / DMM, d = i % DMM;
        float v = b2[d];
        for (int k = 0; k < DMM; k++) v = fmaf(c1[b * DMM + k], W2[k * DMM + d], v);
        c0[i] = gelu_f(v);
    }
    __syncthreads();
    // FiLM: [B,DM] @ [DM,2H]
    for (int i = t; i < BB * 2 * HH; i += blockDim.x) {
        int b = i / (2 * HH), j = i % (2 * HH);
        float v = b_film[j];
        for (int k = 0; k < DMM; k++) v = fmaf(c0[b * DMM + k], W_film[k * 2 * HH + j], v);
        if (j < HH) g_gamma[b * HH + j] = v;
        else        g_beta[b * HH + j - HH] = v;
    }
    // SSM constants
    for (int i = t; i < HH * NN; i += blockDim.x) {
        int h = i / NN;
        float dt = expf(log_dt[h]);
        float ar = A_re[i], ai = A_im[i];
        float dre = dt * ar, dim = dt * ai;
        float e = expf(dre);
        float wre = e * cosf(dim), wim = e * sinf(dim);
        g_wre[i] = wre; g_wim[i] = wim;
        float inv = 1.0f / (ar * ar + ai * ai);
        float nre = wre - 1.0f, nim = wim;                 // exp(dtA)-1
        float qre = (nre * ar + nim * ai) * inv;           // (w-1)/A
        float qim = (nim * ar - nre * ai) * inv;
        float cr = C_re[i], ci = C_im[i];
        g_cre[i] = 2.0f * (cr * qre - ci * qim);
        g_cim[i] = 2.0f * (cr * qim + ci * qre);
        // chunk-jump powers in double (phase can be hundreds of radians)
        double mre = (double)dre, mim = (double)dim;
        double eg = exp(128.0 * mre);
        g_wTre[i] = (float)(eg * cos(128.0 * mim));
        g_wTim[i] = (float)(eg * sin(128.0 * mim));
        double eg2 = exp(2048.0 * mre);
        g_wT16re[i] = (float)(eg2 * cos(2048.0 * mim));
        g_wT16im[i] = (float)(eg2 * sin(2048.0 * mim));
    }
}

// ---------------- K2: u = gelu(x @ W_lin + b_lin), write transposed [B,H,L] ----------------
__global__ __launch_bounds__(256) void k_linear(const float* __restrict__ x,
                                                const float* __restrict__ W,
                                                const float* __restrict__ bias)
{
    extern __shared__ float sm2[];
    float* xs = sm2;                 // [256][65]
    float* Ws = sm2 + 256 * 65;      // [64][64]
    int t = threadIdx.x;
    int b = blockIdx.x >> 7;         // 128 tiles per batch
    int tile = blockIdx.x & 127;
    int l0 = tile * 256;
    const float* xg = x + ((size_t)b * LL + l0) * HH;

    for (int i = t; i < 64 * 64; i += 256) Ws[i] = W[i];
    for (int i = t; i < 256 * 64; i += 256) {
        int l = i >> 6, k = i & 63;
        xs[l * 65 + k] = xg[i];
    }
    __syncthreads();

    int li = t & 63;
    int hb = (t >> 6) * 16;
    u64 acc[4][8];
    #pragma unroll
    for (int p = 0; p < 8; p++) {
        u64 bp = *reinterpret_cast<const u64*>(bias + hb + 2 * p);
        acc[0][p] = bp; acc[1][p] = bp; acc[2][p] = bp; acc[3][p] = bp;
    }
    for (int k = 0; k < 64; k++) {
        float x0 = xs[li * 65 + k];
        float x1 = xs[(li + 64) * 65 + k];
        float x2v = xs[(li + 128) * 65 + k];
        float x3 = xs[(li + 192) * 65 + k];
        u64 xa = pk(x0, x0), xb = pk(x1, x1), xc = pk(x2v, x2v), xd = pk(x3, x3);
        const u64* wrow = reinterpret_cast<const u64*>(Ws + k * 64 + hb);
        #pragma unroll
        for (int p = 0; p < 8; p++) {
            u64 w2 = wrow[p];
            acc[0][p] = fma2(xa, w2, acc[0][p]);
            acc[1][p] = fma2(xb, w2, acc[1][p]);
            acc[2][p] = fma2(xc, w2, acc[2][p]);
            acc[3][p] = fma2(xd, w2, acc[3][p]);
        }
    }
    #pragma unroll
    for (int lg = 0; lg < 4; lg++) {
        int l = l0 + li + lg * 64;
        #pragma unroll
        for (int p = 0; p < 8; p++) {
            float v0, v1; upk(acc[lg][p], v0, v1);
            int h0 = hb + 2 * p;
            g_u[((size_t)b * HH + h0) * LL + l] = gelu_f(v0);
            g_u[((size_t)b * HH + h0 + 1) * LL + l] = gelu_f(v1);
        }
    }
}

// ---------------- K3: chunked parallel scan per (b,h); writes z = y*gamma+beta ----------------
// 1024 blocks (one per (b,h)), 256 threads, chunk T=128.
// SMEM layout is [j][thread] with pad-257 so every warp access is lane-consecutive
// (conflict-free): su[j*257 + t] holds element l = t*128 + j.
#define SUP 257
__global__ __launch_bounds__(256) void k_scan(const float* __restrict__ Dp)
{
    extern __shared__ float sm[];
    float* su = sm;                                            // [128][257] = 32896 f
    float2* sst = reinterpret_cast<float2*>(sm + 128 * SUP);   // [16][257] float2
    float2* gs = reinterpret_cast<float2*>(sm + 128 * SUP + 16 * SUP * 2); // [16][16]
    int t = threadIdx.x;
    int bh = blockIdx.x;
    int h = bh & 63;

    const float* gu = g_u + (size_t)bh * LL;
    // stage: scalar coalesced loads, conflict-free transposed stores
    #pragma unroll 4
    for (int k = 0; k < 128; k++) {
        int i = t + k * 256;
        su[(i & 127) * SUP + (i >> 7)] = gu[i];
    }

    // per-h constants as n-pair f32x2
    u64 wre2[8], wim2[8], nwim2[8], cre2[8], ncim2[8];
    {
        const u64* pwre = reinterpret_cast<const u64*>(g_wre + h * NN);
        const u64* pwim = reinterpret_cast<const u64*>(g_wim + h * NN);
        const u64* pcre = reinterpret_cast<const u64*>(g_cre + h * NN);
        const u64* pcim = reinterpret_cast<const u64*>(g_cim + h * NN);
        #pragma unroll
        for (int p = 0; p < 8; p++) {
            wre2[p] = pwre[p];
            wim2[p] = pwim[p];
            nwim2[p] = pwim[p] ^ NEGMASK;
            cre2[p] = pcre[p];
            ncim2[p] = pcim[p] ^ NEGMASK;
        }
    }
    __syncthreads();

    u64 sre[8], sim[8];
    #pragma unroll
    for (int p = 0; p < 8; p++) { sre[p] = 0ULL; sim[p] = 0ULL; }

    // ---- pass 1: local chunk scan (zero init) ----
    #pragma unroll 4
    for (int j = 0; j < 128; j++) {
        float uv = su[j * SUP + t];
        u64 u2 = pk(uv, uv);
        #pragma unroll
        for (int p = 0; p < 8; p++) {
            u64 t0 = fma2(nwim2[p], sim[p], u2);
            u64 nre = fma2(wre2[p], sre[p], t0);
            sim[p] = fma2(wre2[p], sim[p], mul2(wim2[p], sre[p]));
            sre[p] = nre;
        }
    }
    #pragma unroll
    for (int p = 0; p < 8; p++) {
        float r0, r1, i0, i1; upk(sre[p], r0, r1); upk(sim[p], i0, i1);
        sst[(2 * p) * SUP + t] = make_float2(r0, i0);
        sst[(2 * p + 1) * SUP + t] = make_float2(r1, i1);
    }
    __syncthreads();

    // ---- combine: 2-level scan over 256 chunk states (16 n x 16 groups) ----
    int n = t & 15, g = t >> 4;
    float wtr = g_wTre[h * NN + n], wti = g_wTim[h * NN + n];
    {   // level 1: group totals (zero-init)
        float Ir = 0.f, Ii = 0.f;
        for (int j = 0; j < 16; j++) {
            float2 loc = sst[n * SUP + g * 16 + j];
            float nr = fmaf(wtr, Ir, fmaf(-wti, Ii, loc.x));
            Ii = fmaf(wtr, Ii, fmaf(wti, Ir, loc.y));
            Ir = nr;
        }
        gs[g * 16 + n] = make_float2(Ir, Ii);
    }
    __syncthreads();
    if (t < 16) {   // level 2: sequential over 16 groups with w^2048
        float wr = g_wT16re[h * NN + t], wi = g_wT16im[h * NN + t];
        float Pr = 0.f, Pi = 0.f;
        for (int gg = 0; gg < 16; gg++) {
            float2 tmp = gs[gg * 16 + t];
            gs[gg * 16 + t] = make_float2(Pr, Pi);
            float nr = fmaf(wr, Pr, fmaf(-wi, Pi, tmp.x));
            Pi = fmaf(wr, Pi, fmaf(wi, Pr, tmp.y));
            Pr = nr;
        }
    }
    __syncthreads();
    {   // level 3: per-chunk incoming states (overwrite sst in place)
        float2 I0 = gs[g * 16 + n];
        float Ir = I0.x, Ii = I0.y;
        for (int j = 0; j < 16; j++) {
            int c = g * 16 + j;
            float2 loc = sst[n * SUP + c];
            sst[n * SUP + c] = make_float2(Ir, Ii);
            float nr = fmaf(wtr, Ir, fmaf(-wti, Ii, loc.x));
            Ii = fmaf(wtr, Ii, fmaf(wti, Ir, loc.y));
            Ir = nr;
        }
    }
    __syncthreads();

    // ---- pass 2: rescan with incoming state, emit z = y*gamma + beta ----
    #pragma unroll
    for (int p = 0; p < 8; p++) {
        float2 a = sst[(2 * p) * SUP + t];
        float2 bq = sst[(2 * p + 1) * SUP + t];
        sre[p] = pk(a.x, bq.x);
        sim[p] = pk(a.y, bq.y);
    }
    float dcoef = Dp[h];
    float gam = g_gamma[bh];
    float bet = g_beta[bh];

    #pragma unroll 4
    for (int j = 0; j < 128; j++) {
        float uv = su[j * SUP + t];
        u64 u2 = pk(uv, uv);
        u64 accA = 0ULL, accB = 0ULL;
        #pragma unroll
        for (int p = 0; p < 8; p++) {
            u64 t0 = fma2(nwim2[p], sim[p], u2);
            u64 nre = fma2(wre2[p], sre[p], t0);
            sim[p] = fma2(wre2[p], sim[p], mul2(wim2[p], sre[p]));
            sre[p] = nre;
            accA = fma2(cre2[p], nre, accA);
            accB = fma2(ncim2[p], sim[p], accB);
        }
        u64 acc = add2(accA, accB);
        float alo, ahi; upk(acc, alo, ahi);
        float y = alo + ahi;
        y = fmaf(dcoef, uv, y);
        su[j * SUP + t] = fmaf(y, gam, bet);
    }
    __syncthreads();

    float* gz = g_z + (size_t)bh * LL;
    #pragma unroll 4
    for (int k = 0; k < 128; k++) {
        int i = t + k * 256;
        gz[i] = su[(i & 127) * SUP + (i >> 7)];
    }
}

// ---------------- K4: out[b,l,h] = x[b,l,h] * gelu(z[b,h,l]) (float4 + SMEM transpose) ----------------
__global__ __launch_bounds__(256) void k_epilogue(const float* __restrict__ x,
                                                  float* __restrict__ out)
{
    __shared__ float zt[64 * 65];
    int t = threadIdx.x;
    int b = blockIdx.x >> 9;      // 512 tiles per batch
    int tile = blockIdx.x & 511;
    int l0 = tile * 64;

    // load z tile [64 h][64 l] with float4 along l
    #pragma unroll
    for (int i = t; i < 1024; i += 256) {
        int hh = i >> 4, q = i & 15;
        float4 v = *reinterpret_cast<const float4*>(
            g_z + ((size_t)b * HH + hh) * LL + l0 + 4 * q);
        float* d = zt + hh * 65 + 4 * q;
        d[0] = v.x; d[1] = v.y; d[2] = v.z; d[3] = v.w;
    }
    __syncthreads();

    // emit: per (l, 4h) group with float4 x load / out store
    #pragma unroll
    for (int i = t; i < 1024; i += 256) {
        int l = i >> 4, hq = i & 15;
        float z0 = zt[(4 * hq + 0) * 65 + l];
        float z1 = zt[(4 * hq + 1) * 65 + l];
        float z2 = zt[(4 * hq + 2) * 65 + l];
        float z3 = zt[(4 * hq + 3) * 65 + l];
        size_t base = ((size_t)b * LL + l0 + l) * HH + 4 * hq;
        float4 xv = *reinterpret_cast<const float4*>(x + base);
        float4 o;
        o.x = xv.x * gelu_f(z0);
        o.y = xv.y * gelu_f(z1);
        o.z = xv.z * gelu_f(z2);
        o.w = xv.w * gelu_f(z3);
        *reinterpret_cast<float4*>(out + base) = o;
    }
}

// ---------------- launch ----------------
extern "C" void kernel_launch(void* const* d_in, const int* in_sizes, int n_in,
                              void* d_out, int out_size)
{
    const float* x      = (const float*)d_in[0];
    const float* cp     = (const float*)d_in[1];
    const float* W0     = (const float*)d_in[2];
    const float* b0     = (const float*)d_in[3];
    const float* W1     = (const float*)d_in[4];
    const float* b1     = (const float*)d_in[5];
    const float* W2     = (const float*)d_in[6];
    const float* b2     = (const float*)d_in[7];
    const float* W_lin  = (const float*)d_in[8];
    const float* b_lin  = (const float*)d_in[9];
    const float* log_dt = (const float*)d_in[10];
    const float* A_re   = (const float*)d_in[11];
    const float* A_im   = (const float*)d_in[12];
    const float* C_re   = (const float*)d_in[13];
    const float* C_im   = (const float*)d_in[14];
    const float* Dv     = (const float*)d_in[15];
    const float* W_film = (const float*)d_in[16];
    const float* b_film = (const float*)d_in[17];
    float* out = (float*)d_out;

    const int smem_lin  = (256 * 65 + 64 * 64) * 4;                       // 82944 B
    const int smem_scan = (128 * SUP + 16 * SUP * 2 + 16 * 16 * 2) * 4;   // 166528 B
    cudaFuncSetAttribute(k_linear, cudaFuncAttributeMaxDynamicSharedMemorySize, smem_lin);
    cudaFuncSetAttribute(k_scan, cudaFuncAttributeMaxDynamicSharedMemorySize, smem_scan);

    k_setup<<<1, 256>>>(cp, W0, b0, W1, b1, W2, b2,
                        log_dt, A_re, A_im, C_re, C_im, W_film, b_film);
    k_linear<<<BB * (LL / 256), 256, smem_lin>>>(x, W_lin, b_lin);
    k_scan<<<BB * HH, 256, smem_scan>>>(Dv);
    k_epilogue<<<BB * (LL / 64), 256>>>(x, out);
}

// round 3
// speedup vs baseline: 1.4164x; 1.0042x over previous
#include <cuda_runtime.h>
#include <cstdint>
#include <cstddef>

#define BB 16
#define LL 32768
#define HH 64
#define NN 16
#define DMM 32

typedef unsigned long long u64;

// ---------------- scratch (device globals) ----------------
__device__ float g_u[(size_t)BB * HH * LL];   // gelu(x@W_lin) transposed to [B,H,L]
__device__ float g_z[(size_t)BB * HH * LL];   // FiLM-affine SSM output [B,H,L]
__device__ __align__(16) float g_w1re[HH * NN], g_w1im[HH * NN];
__device__ __align__(16) float g_w2re[HH * NN], g_w2im[HH * NN];
__device__ __align__(16) float g_w3re[HH * NN], g_w3im[HH * NN];
__device__ __align__(16) float g_w4re[HH * NN], g_w4im[HH * NN];
__device__ __align__(16) float g_cre[HH * NN], g_cim[HH * NN];     // 2*C'
__device__ __align__(16) float g_cwre[HH * NN], g_cwim[HH * NN];   // 2*C'*w
__device__ float g_wTre[HH * NN], g_wTim[HH * NN];     // w^128
__device__ float g_wT16re[HH * NN], g_wT16im[HH * NN]; // w^2048
__device__ float g_gamma[BB * HH], g_beta[BB * HH];
__device__ float g_rcd[HH];                            // sum_n 2Re(C') + D

// ---------------- f32x2 helpers ----------------
__device__ __forceinline__ u64 pk(float lo, float hi) {
    u64 r; asm("mov.b64 %0, {%1,%2};" : "=l"(r) : "f"(lo), "f"(hi)); return r;
}
__device__ __forceinline__ void upk(u64 a, float& lo, float& hi) {
    asm("mov.b64 {%0,%1}, %2;" : "=f"(lo), "=f"(hi) : "l"(a));
}
__device__ __forceinline__ u64 fma2(u64 a, u64 b, u64 c) {
    u64 d; asm("fma.rn.f32x2 %0, %1, %2, %3;" : "=l"(d) : "l"(a), "l"(b), "l"(c)); return d;
}
__device__ __forceinline__ u64 mul2(u64 a, u64 b) {
    u64 d; asm("mul.rn.f32x2 %0, %1, %2;" : "=l"(d) : "l"(a), "l"(b)); return d;
}
__device__ __forceinline__ u64 add2(u64 a, u64 b) {
    u64 d; asm("add.rn.f32x2 %0, %1, %2;" : "=l"(d) : "l"(a), "l"(b)); return d;
}
#define NEGMASK 0x8000000080000000ULL

// jax.nn.gelu (approximate=True)
__device__ __forceinline__ float gelu_f(float x) {
    float x3 = x * x * x;
    float z = 0.7978845608028654f * fmaf(0.044715f, x3, x);
    float az = fabsf(z);
    float e = __expf(2.0f * az);
    float t = 1.0f - __fdividef(2.0f, e + 1.0f);
    t = copysignf(t, z);
    return 0.5f * x * (1.0f + t);
}

// ---------------- K0: SSM constants (8 blocks x 128 threads, 1 item/thread) ----------------
__global__ void k_setup_ssm(const float* __restrict__ log_dt,
                            const float* __restrict__ A_re, const float* __restrict__ A_im,
                            const float* __restrict__ C_re, const float* __restrict__ C_im)
{
    int i = blockIdx.x * blockDim.x + threadIdx.x;
    if (i >= HH * NN) return;
    int h = i / NN;
    float dt = expf(log_dt[h]);
    float ar = A_re[i], ai = A_im[i];
    double mre = (double)dt * (double)ar, mim = (double)dt * (double)ai;

    double e1 = exp(mre);
    float wre = (float)(e1 * cos(mim)), wim = (float)(e1 * sin(mim));
    g_w1re[i] = wre; g_w1im[i] = wim;
    double e2 = exp(2.0 * mre);
    g_w2re[i] = (float)(e2 * cos(2.0 * mim)); g_w2im[i] = (float)(e2 * sin(2.0 * mim));
    double e3 = exp(3.0 * mre);
    g_w3re[i] = (float)(e3 * cos(3.0 * mim)); g_w3im[i] = (float)(e3 * sin(3.0 * mim));
    double e4 = exp(4.0 * mre);
    g_w4re[i] = (float)(e4 * cos(4.0 * mim)); g_w4im[i] = (float)(e4 * sin(4.0 * mim));
    double eT = exp(128.0 * mre);
    g_wTre[i] = (float)(eT * cos(128.0 * mim)); g_wTim[i] = (float)(eT * sin(128.0 * mim));
    double eG = exp(2048.0 * mre);
    g_wT16re[i] = (float)(eG * cos(2048.0 * mim)); g_wT16im[i] = (float)(eG * sin(2048.0 * mim));

    // C' = C * (exp(dtA)-1)/A ;   store 2*C' and 2*C'*w
    float inv = 1.0f / (ar * ar + ai * ai);
    float nre = wre - 1.0f, nim = wim;
    float qre = (nre * ar + nim * ai) * inv;
    float qim = (nim * ar - nre * ai) * inv;
    float cr = C_re[i], ci = C_im[i];
    float c2re = 2.0f * (cr * qre - ci * qim);
    float c2im = 2.0f * (cr * qim + ci * qre);
    g_cre[i] = c2re; g_cim[i] = c2im;
    g_cwre[i] = c2re * wre - c2im * wim;
    g_cwim[i] = c2re * wim + c2im * wre;
}

// ---------------- K1: conditioning MLP + FiLM + rcd ----------------
__global__ void k_setup_mlp(const float* __restrict__ cp,
                            const float* __restrict__ W0, const float* __restrict__ b0,
                            const float* __restrict__ W1, const float* __restrict__ b1,
                            const float* __restrict__ W2, const float* __restrict__ b2,
                            const float* __restrict__ W_film, const float* __restrict__ b_film,
                            const float* __restrict__ Dp)
{
    __shared__ float c0[BB * DMM];
    __shared__ float c1[BB * DMM];
    int t = threadIdx.x;

    for (int i = t; i < BB * DMM; i += blockDim.x) {
        int b = i / DMM, d = i % DMM;
        float v = fmaf(cp[b * 2 + 0], W0[d], fmaf(cp[b * 2 + 1], W0[DMM + d], b0[d]));
        c0[i] = gelu_f(v);
    }
    __syncthreads();
    for (int i = t; i < BB * DMM; i += blockDim.x) {
        int b = i / DMM, d = i % DMM;
        float v = b1[d];
        for (int k = 0; k < DMM; k++) v = fmaf(c0[b * DMM + k], W1[k * DMM + d], v);
        c1[i] = gelu_f(v);
    }
    __syncthreads();
    for (int i = t; i < BB * DMM; i += blockDim.x) {
        int b = i / DMM, d = i % DMM;
        float v = b2[d];
        for (int k = 0; k < DMM; k++) v = fmaf(c1[b * DMM + k], W2[k * DMM + d], v);
        c0[i] = gelu_f(v);
    }
    __syncthreads();
    for (int i = t; i < BB * 2 * HH; i += blockDim.x) {
        int b = i / (2 * HH), j = i % (2 * HH);
        float v = b_film[j];
        for (int k = 0; k < DMM; k++) v = fmaf(c0[b * DMM + k], W_film[k * 2 * HH + j], v);
        if (j < HH) g_gamma[b * HH + j] = v;
        else        g_beta[b * HH + j - HH] = v;
    }
    // rcd[h] = sum_n 2Re(C'_n) + D[h]  (g_cre written by k_setup_ssm, prior kernel)
    for (int h = t; h < HH; h += blockDim.x) {
        float s = Dp[h];
        for (int n = 0; n < NN; n++) s += g_cre[h * NN + n];
        g_rcd[h] = s;
    }
}

// ---------------- K2: u = gelu(x @ W_lin + b_lin), write transposed [B,H,L] ----------------
__global__ __launch_bounds__(256) void k_linear(const float* __restrict__ x,
                                                const float* __restrict__ W,
                                                const float* __restrict__ bias)
{
    extern __shared__ float sm2[];
    float* xs = sm2;                 // [256][65]
    float* Ws = sm2 + 256 * 65;      // [64][64]
    int t = threadIdx.x;
    int b = blockIdx.x >> 7;
    int tile = blockIdx.x & 127;
    int l0 = tile * 256;
    const float* xg = x + ((size_t)b * LL + l0) * HH;

    for (int i = t; i < 64 * 64; i += 256) Ws[i] = W[i];
    for (int i = t; i < 256 * 64; i += 256) {
        int l = i >> 6, k = i & 63;
        xs[l * 65 + k] = xg[i];
    }
    __syncthreads();

    int li = t & 63;
    int hb = (t >> 6) * 16;
    u64 acc[4][8];
    #pragma unroll
    for (int p = 0; p < 8; p++) {
        u64 bp = *reinterpret_cast<const u64*>(bias + hb + 2 * p);
        acc[0][p] = bp; acc[1][p] = bp; acc[2][p] = bp; acc[3][p] = bp;
    }
    for (int k = 0; k < 64; k++) {
        float x0 = xs[li * 65 + k];
        float x1 = xs[(li + 64) * 65 + k];
        float x2v = xs[(li + 128) * 65 + k];
        float x3 = xs[(li + 192) * 65 + k];
        u64 xa = pk(x0, x0), xb = pk(x1, x1), xc = pk(x2v, x2v), xd = pk(x3, x3);
        const u64* wrow = reinterpret_cast<const u64*>(Ws + k * 64 + hb);
        #pragma unroll
        for (int p = 0; p < 8; p++) {
            u64 w2 = wrow[p];
            acc[0][p] = fma2(xa, w2, acc[0][p]);
            acc[1][p] = fma2(xb, w2, acc[1][p]);
            acc[2][p] = fma2(xc, w2, acc[2][p]);
            acc[3][p] = fma2(xd, w2, acc[3][p]);
        }
    }
    #pragma unroll
    for (int lg = 0; lg < 4; lg++) {
        int l = l0 + li + lg * 64;
        #pragma unroll
        for (int p = 0; p < 8; p++) {
            float v0, v1; upk(acc[lg][p], v0, v1);
            int h0 = hb + 2 * p;
            g_u[((size_t)b * HH + h0) * LL + l] = gelu_f(v0);
            g_u[((size_t)b * HH + h0 + 1) * LL + l] = gelu_f(v1);
        }
    }
}

// ---------------- K3: chunked parallel scan per (b,h) ----------------
// SMEM [j][thread], pad 257 (conflict-free). su[j*257+t] = element l = t*128+j.
#define SUP 257
__global__ __launch_bounds__(256) void k_scan(const float* __restrict__ Dp)
{
    extern __shared__ float sm[];
    float* su = sm;                                            // [128][257]
    float2* sst = reinterpret_cast<float2*>(sm + 128 * SUP);   // [16][257] float2
    float2* gs = reinterpret_cast<float2*>(sm + 128 * SUP + 16 * SUP * 2); // [16][16]
    int t = threadIdx.x;
    int bh = blockIdx.x;
    int h = bh & 63;

    const float* gu = g_u + (size_t)bh * LL;
    #pragma unroll 4
    for (int k = 0; k < 128; k++) {
        int i = t + k * 256;
        su[(i & 127) * SUP + (i >> 7)] = gu[i];
    }

    // pass-1 constants: w^1..w^4 per state-pair p
    u64 w1re[8], w1im[8], w2re[8], w2im[8], w3re[8], w3im[8], w4re[8], w4im[8];
    {
        const u64* p1r = reinterpret_cast<const u64*>(g_w1re + h * NN);
        const u64* p1i = reinterpret_cast<const u64*>(g_w1im + h * NN);
        const u64* p2r = reinterpret_cast<const u64*>(g_w2re + h * NN);
        const u64* p2i = reinterpret_cast<const u64*>(g_w2im + h * NN);
        const u64* p3r = reinterpret_cast<const u64*>(g_w3re + h * NN);
        const u64* p3i = reinterpret_cast<const u64*>(g_w3im + h * NN);
        const u64* p4r = reinterpret_cast<const u64*>(g_w4re + h * NN);
        const u64* p4i = reinterpret_cast<const u64*>(g_w4im + h * NN);
        #pragma unroll
        for (int p = 0; p < 8; p++) {
            w1re[p] = p1r[p]; w1im[p] = p1i[p];
            w2re[p] = p2r[p]; w2im[p] = p2i[p];
            w3re[p] = p3r[p]; w3im[p] = p3i[p];
            w4re[p] = p4r[p]; w4im[p] = p4i[p];
        }
    }
    __syncthreads();

    u64 sre[8], sim[8];
    #pragma unroll
    for (int p = 0; p < 8; p++) { sre[p] = 0ULL; sim[p] = 0ULL; }

    // ---- pass 1: step-4 grouped local scan ----
    #pragma unroll 1
    for (int q = 0; q < 32; q++) {
        float ua = su[(4 * q + 0) * SUP + t];
        float ub = su[(4 * q + 1) * SUP + t];
        float uc = su[(4 * q + 2) * SUP + t];
        float ud = su[(4 * q + 3) * SUP + t];
        u64 u1 = pk(ua, ua), u2 = pk(ub, ub), u3 = pk(uc, uc), u4 = pk(ud, ud);
        #pragma unroll
        for (int p = 0; p < 8; p++) {
            // v = w^3 u1 + w^2 u2 + w u3 + u4
            u64 vre = fma2(w3re[p], u1, fma2(w2re[p], u2, fma2(w1re[p], u3, u4)));
            u64 vim = fma2(w3im[p], u1, fma2(w2im[p], u2, mul2(w1im[p], u3)));
            // s = w^4 s + v
            u64 nw4 = w4im[p] ^ NEGMASK;
            u64 nre = fma2(w4re[p], sre[p], fma2(nw4, sim[p], vre));
            sim[p] = fma2(w4re[p], sim[p], fma2(w4im[p], sre[p], vim));
            sre[p] = nre;
        }
    }
    #pragma unroll
    for (int p = 0; p < 8; p++) {
        float r0, r1, i0, i1; upk(sre[p], r0, r1); upk(sim[p], i0, i1);
        sst[(2 * p) * SUP + t] = make_float2(r0, i0);
        sst[(2 * p + 1) * SUP + t] = make_float2(r1, i1);
    }
    __syncthreads();

    // ---- combine over 256 chunk states (16 n x 16 groups) ----
    int n = t & 15, g = t >> 4;
    float wtr = g_wTre[h * NN + n], wti = g_wTim[h * NN + n];
    {
        float Ir = 0.f, Ii = 0.f;
        for (int j = 0; j < 16; j++) {
            float2 loc = sst[n * SUP + g * 16 + j];
            float nr = fmaf(wtr, Ir, fmaf(-wti, Ii, loc.x));
            Ii = fmaf(wtr, Ii, fmaf(wti, Ir, loc.y));
            Ir = nr;
        }
        gs[g * 16 + n] = make_float2(Ir, Ii);
    }
    __syncthreads();
    if (t < 16) {
        float wr = g_wT16re[h * NN + t], wi = g_wT16im[h * NN + t];
        float Pr = 0.f, Pi = 0.f;
        for (int gg = 0; gg < 16; gg++) {
            float2 tmp = gs[gg * 16 + t];
            gs[gg * 16 + t] = make_float2(Pr, Pi);
            float nr = fmaf(wr, Pr, fmaf(-wi, Pi, tmp.x));
            Pi = fmaf(wr, Pi, fmaf(wi, Pr, tmp.y));
            Pr = nr;
        }
    }
    __syncthreads();
    {
        float2 I0 = gs[g * 16 + n];
        float Ir = I0.x, Ii = I0.y;
        for (int j = 0; j < 16; j++) {
            int c = g * 16 + j;
            float2 loc = sst[n * SUP + c];
            sst[n * SUP + c] = make_float2(Ir, Ii);
            float nr = fmaf(wtr, Ir, fmaf(-wti, Ii, loc.x));
            Ii = fmaf(wtr, Ii, fmaf(wti, Ir, loc.y));
            Ir = nr;
        }
    }
    __syncthreads();

    // ---- pass 2: step-2 rescan, emit z = y*gamma + beta ----
    #pragma unroll
    for (int p = 0; p < 8; p++) {
        float2 a = sst[(2 * p) * SUP + t];
        float2 bq = sst[(2 * p + 1) * SUP + t];
        sre[p] = pk(a.x, bq.x);
        sim[p] = pk(a.y, bq.y);
    }
    // pass-2 constants: reuse w1,w2; add 2C'w (neg im) and 2C' (neg im)
    u64 cwre2[8], ncwim2[8], cre2[8], ncim2[8];
    {
        const u64* pcwr = reinterpret_cast<const u64*>(g_cwre + h * NN);
        const u64* pcwi = reinterpret_cast<const u64*>(g_cwim + h * NN);
        const u64* pcr = reinterpret_cast<const u64*>(g_cre + h * NN);
        const u64* pci = reinterpret_cast<const u64*>(g_cim + h * NN);
        #pragma unroll
        for (int p = 0; p < 8; p++) {
            cwre2[p] = pcwr[p];
            ncwim2[p] = pcwi[p] ^ NEGMASK;
            cre2[p] = pcr[p];
            ncim2[p] = pci[p] ^ NEGMASK;
        }
    }
    float dcoef = Dp[h];
    float rcd = g_rcd[h];
    float gam = g_gamma[bh];
    float bet = g_beta[bh];

    #pragma unroll 1
    for (int q = 0; q < 64; q++) {
        float ua = su[(2 * q) * SUP + t];
        float ub = su[(2 * q + 1) * SUP + t];
        u64 u1 = pk(ua, ua), u2 = pk(ub, ub);
        u64 a1 = 0ULL, b1 = 0ULL, a2 = 0ULL, b2 = 0ULL;
        #pragma unroll
        for (int p = 0; p < 8; p++) {
            // y1 contribution from incoming state s0
            a1 = fma2(cwre2[p], sre[p], a1);
            b1 = fma2(ncwim2[p], sim[p], b1);
            // v = w u1 + u2
            u64 vre = fma2(w1re[p], u1, u2);
            u64 vim = mul2(w1im[p], u1);
            // s2 = w^2 s0 + v
            u64 nw2 = w2im[p] ^ NEGMASK;
            u64 nre = fma2(w2re[p], sre[p], fma2(nw2, sim[p], vre));
            sim[p] = fma2(w2re[p], sim[p], fma2(w2im[p], sre[p], vim));
            sre[p] = nre;
            // y2 from s2
            a2 = fma2(cre2[p], nre, a2);
            b2 = fma2(ncim2[p], sim[p], b2);
        }
        u64 s1 = add2(a1, b1);
        u64 s2 = add2(a2, b2);
        float y1lo, y1hi, y2lo, y2hi;
        upk(s1, y1lo, y1hi); upk(s2, y2lo, y2hi);
        float y1 = fmaf(rcd, ua, y1lo + y1hi);
        float y2 = fmaf(dcoef, ub, y2lo + y2hi);
        su[(2 * q) * SUP + t] = fmaf(y1, gam, bet);
        su[(2 * q + 1) * SUP + t] = fmaf(y2, gam, bet);
    }
    __syncthreads();

    float* gz = g_z + (size_t)bh * LL;
    #pragma unroll 4
    for (int k = 0; k < 128; k++) {
        int i = t + k * 256;
        gz[i] = su[(i & 127) * SUP + (i >> 7)];
    }
}

// ---------------- K4: out[b,l,h] = x[b,l,h] * gelu(z[b,h,l]) ----------------
__global__ __launch_bounds__(256) void k_epilogue(const float* __restrict__ x,
                                                  float* __restrict__ out)
{
    __shared__ float zt[64 * 65];
    int t = threadIdx.x;
    int b = blockIdx.x >> 9;
    int tile = blockIdx.x & 511;
    int l0 = tile * 64;

    #pragma unroll
    for (int i = t; i < 1024; i += 256) {
        int hh = i >> 4, q = i & 15;
        float4 v = *reinterpret_cast<const float4*>(
            g_z + ((size_t)b * HH + hh) * LL + l0 + 4 * q);
        float* d = zt + hh * 65 + 4 * q;
        d[0] = v.x; d[1] = v.y; d[2] = v.z; d[3] = v.w;
    }
    __syncthreads();

    #pragma unroll
    for (int i = t; i < 1024; i += 256) {
        int l = i >> 4, hq = i & 15;
        float z0 = zt[(4 * hq + 0) * 65 + l];
        float z1 = zt[(4 * hq + 1) * 65 + l];
        float z2 = zt[(4 * hq + 2) * 65 + l];
        float z3 = zt[(4 * hq + 3) * 65 + l];
        size_t base = ((size_t)b * LL + l0 + l) * HH + 4 * hq;
        float4 xv = *reinterpret_cast<const float4*>(x + base);
        float4 o;
        o.x = xv.x * gelu_f(z0);
        o.y = xv.y * gelu_f(z1);
        o.z = xv.z * gelu_f(z2);
        o.w = xv.w * gelu_f(z3);
        *reinterpret_cast<float4*>(out + base) = o;
    }
}

// ---------------- launch ----------------
extern "C" void kernel_launch(void* const* d_in, const int* in_sizes, int n_in,
                              void* d_out, int out_size)
{
    const float* x      = (const float*)d_in[0];
    const float* cp     = (const float*)d_in[1];
    const float* W0     = (const float*)d_in[2];
    const float* b0     = (const float*)d_in[3];
    const float* W1     = (const float*)d_in[4];
    const float* b1     = (const float*)d_in[5];
    const float* W2     = (const float*)d_in[6];
    const float* b2     = (const float*)d_in[7];
    const float* W_lin  = (const float*)d_in[8];
    const float* b_lin  = (const float*)d_in[9];
    const float* log_dt = (const float*)d_in[10];
    const float* A_re   = (const float*)d_in[11];
    const float* A_im   = (const float*)d_in[12];
    const float* C_re   = (const float*)d_in[13];
    const float* C_im   = (const float*)d_in[14];
    const float* Dv     = (const float*)d_in[15];
    const float* W_film = (const float*)d_in[16];
    const float* b_film = (const float*)d_in[17];
    float* out = (float*)d_out;

    const int smem_lin  = (256 * 65 + 64 * 64) * 4;
    const int smem_scan = (128 * SUP + 16 * SUP * 2 + 16 * 16 * 2) * 4;
    cudaFuncSetAttribute(k_linear, cudaFuncAttributeMaxDynamicSharedMemorySize, smem_lin);
    cudaFuncSetAttribute(k_scan, cudaFuncAttributeMaxDynamicSharedMemorySize, smem_scan);

    k_setup_ssm<<<8, 128>>>(log_dt, A_re, A_im, C_re, C_im);
    k_setup_mlp<<<1, 256>>>(cp, W0, b0, W1, b1, W2, b2, W_film, b_film, Dv);
    k_linear<<<BB * (LL / 256), 256, smem_lin>>>(x, W_lin, b_lin);
    k_scan<<<BB * HH, 256, smem_scan>>>(Dv);
    k_epilogue<<<BB * (LL / 64), 256>>>(x, out);
}